// round 2
// baseline (speedup 1.0000x reference)
#include <cuda_runtime.h>

// BatchBlur: per-sample 15x15 depthwise blur with reflect pad.
// x: (32,3,512,512) f32, kernel: (32,15,15) f32, out: (32,3,512,512) f32.

#define BB 32
#define CC 3
#define HH 512
#define WW 512
#define LL 15
#define PP 7

#define TW 128                 // output cols per CTA
#define TH 32                  // output rows per CTA
#define IN_ROWS (TH + LL - 1)  // 46
#define ROW_F 142              // floats per smem tile row (TW + 14)

typedef unsigned long long u64;

__device__ __forceinline__ void ffma2(u64& acc, u64 a, u64 b) {
    // packed fp32 FMA: acc.lo += a.lo*b.lo ; acc.hi += a.hi*b.hi
    asm("fma.rn.f32x2 %0, %1, %2, %0;" : "+l"(acc) : "l"(a), "l"(b));
}

// build pair {a.hi, b.lo}
__device__ __forceinline__ u64 hilo(u64 a, u64 b) {
    u64 r;
    asm("{\n\t"
        ".reg .b32 alo, ahi, blo, bhi;\n\t"
        "mov.b64 {alo, ahi}, %1;\n\t"
        "mov.b64 {blo, bhi}, %2;\n\t"
        "mov.b64 %0, {ahi, blo};\n\t"
        "}"
        : "=l"(r) : "l"(a), "l"(b));
    return r;
}

// One input row's contribution to one or two output rows.
// rowp: swizzled smem row base; off[c]: per-thread swizzled float offsets (15 pairs)
// k0/k1: duplicated kernel rows (float2 per tap)
template <bool DO0, bool DO1>
__device__ __forceinline__ void row_step(const float* rowp, const int* off,
                                         const float2* k0, const float2* k1,
                                         u64* acc0, u64* acc1) {
    u64 pe[15];
#pragma unroll
    for (int c = 0; c < 15; c++)
        pe[c] = *reinterpret_cast<const u64*>(rowp + off[c]);
    u64 po[14];
#pragma unroll
    for (int c = 0; c < 14; c++)
        po[c] = hilo(pe[c], pe[c + 1]);

#pragma unroll
    for (int dx = 0; dx < 15; dx++) {
        u64 kk0 = 0, kk1 = 0;
        if (DO0) kk0 = *reinterpret_cast<const u64*>(&k0[dx]);
        if (DO1) kk1 = *reinterpret_cast<const u64*>(&k1[dx]);
        const u64* src = (dx & 1) ? &po[(dx - 1) >> 1] : &pe[dx >> 1];
#pragma unroll
        for (int i = 0; i < 8; i++) {
            if (DO0) ffma2(acc0[i], src[i], kk0);
            if (DO1) ffma2(acc1[i], src[i], kk1);
        }
    }
}

__global__ __launch_bounds__(128) void batchblur_kernel(
    const float* __restrict__ x, const float* __restrict__ ker,
    float* __restrict__ out) {
    __shared__ __align__(16) float s_in[IN_ROWS * ROW_F];
    __shared__ float2 s_k[LL * LL];

    const int tid = threadIdx.x;
    const int tx = tid & 7;    // 8 threads across x, 16 px each
    const int ty = tid >> 3;   // 16 threads across y, 2 rows each

    const int x0 = blockIdx.x * TW;
    const int y0 = blockIdx.y * TH;
    const int img = blockIdx.z;   // b*3 + c
    const int b = img / CC;

    const float* xin = x + (size_t)img * (HH * WW);

    // kernel, duplicated into both float2 halves for f32x2 broadcast
    for (int i = tid; i < LL * LL; i += 128) {
        float v = ker[b * (LL * LL) + i];
        s_k[i] = make_float2(v, v);
    }

    // input tile load: reflect pad + pair-granularity XOR swizzle
    for (int idx = tid; idx < IN_ROWS * ROW_F; idx += 128) {
        int r = idx / ROW_F;
        int f = idx - r * ROW_F;
        int gy = y0 + r - PP;
        gy = gy < 0 ? -gy : (gy >= HH ? 2 * HH - 2 - gy : gy);
        int gx = x0 + f - PP;
        gx = gx < 0 ? -gx : (gx >= WW ? 2 * WW - 2 - gx : gx);
        float v = xin[gy * WW + gx];
        int p = f >> 1;
        int q = p ^ ((p >> 3) & 7);
        s_in[r * ROW_F + (q << 1) + (f & 1)] = v;
    }
    __syncthreads();

    // precompute swizzled float offsets of this thread's 15 window pairs
    int off[15];
#pragma unroll
    for (int c = 0; c < 15; c++) {
        int q;
        if (c < 8) {
            q = (tx << 3) | (c ^ tx);
        } else {
            int t1 = tx + 1;
            q = (t1 << 3) + ((c - 8) ^ (t1 & 7));
        }
        off[c] = q << 1;
    }

    u64 acc0[8], acc1[8];
#pragma unroll
    for (int i = 0; i < 8; i++) { acc0[i] = 0ull; acc1[i] = 0ull; }

    const int R0 = 2 * ty;   // first input row of this thread's window

    // rr = 0: only out-row0 (kernel row 0)
    row_step<true, false>(s_in + (size_t)(R0 + 0) * ROW_F, off, &s_k[0], &s_k[0],
                          acc0, acc1);
#pragma unroll 1
    for (int rr = 1; rr < 15; rr++) {
        row_step<true, true>(s_in + (size_t)(R0 + rr) * ROW_F, off,
                             &s_k[rr * 15], &s_k[(rr - 1) * 15], acc0, acc1);
    }
    // rr = 15: only out-row1 (kernel row 14)
    row_step<false, true>(s_in + (size_t)(R0 + 15) * ROW_F, off, &s_k[0],
                          &s_k[14 * 15], acc0, acc1);

    // stage outputs in smem (reuse tile), then write coalesced
    __syncthreads();
    float* s_out = s_in;   // 128*32 = 4096 floats <= 6532
#pragma unroll
    for (int i = 0; i < 8; i++) {
        *reinterpret_cast<u64*>(&s_out[(2 * ty) * TW + 16 * tx + 2 * i]) = acc0[i];
        *reinterpret_cast<u64*>(&s_out[(2 * ty + 1) * TW + 16 * tx + 2 * i]) = acc1[i];
    }
    __syncthreads();

    float* obase = out + (size_t)img * (HH * WW) + (size_t)y0 * WW + x0;
    const int V = (TW * TH) / 4;   // 1024 float4
#pragma unroll
    for (int v = tid; v < V; v += 128) {
        int r = v >> 5;              // TW/4 = 32 float4 per row
        int cidx = v & 31;
        float4 val = reinterpret_cast<const float4*>(s_out)[v];
        *reinterpret_cast<float4*>(obase + (size_t)r * WW + cidx * 4) = val;
    }
}

extern "C" void kernel_launch(void* const* d_in, const int* in_sizes, int n_in,
                              void* d_out, int out_size) {
    const float* x = (const float*)d_in[0];
    const float* k = (const float*)d_in[1];
    float* out = (float*)d_out;
    dim3 grid(WW / TW, HH / TH, BB * CC);
    batchblur_kernel<<<grid, 128>>>(x, k, out);
}